// round 3
// baseline (speedup 1.0000x reference)
#include <cuda_runtime.h>
#include <math.h>

#define TT 2048
#define HH 8
#define DD 128
#define MM 4096
#define LL 512
#define RC 16                     // row chunks for attn column-sum
#define ROWS_PER_CHUNK (TT / RC)  // 128

// ---------------- device scratch (no allocations allowed) ----------------
__device__ float g_part[HH * RC * TT];   // attn partial column sums
__device__ float g_knorm[HH * TT];
__device__ float g_vnorm[HH * TT];
__device__ float g_qnorm[HH * TT];
__device__ float g_enorm[TT];
__device__ float g_prio[HH * TT];
__device__ int   g_keep[HH * LL];

// ---------------- 1) attn weighted column partial sums ----------------
// attn[h, i, t] * (i+1), summed over i within a 128-row chunk.
// grid: (TT/256, RC, HH), block: 256. Coalesced: consecutive threads ->
// consecutive columns -> 128B lines per warp per row.
__global__ void attn_partial_kernel(const float* __restrict__ attn) {
    int col = blockIdx.x * 256 + threadIdx.x;
    int rc  = blockIdx.y;
    int h   = blockIdx.z;
    int row0 = rc * ROWS_PER_CHUNK;
    const float* base = attn + ((size_t)h * TT + row0) * TT + col;
    float s = 0.0f;
#pragma unroll 8
    for (int i = 0; i < ROWS_PER_CHUNK; ++i) {
        s += base[(size_t)i * TT] * (float)(row0 + i + 1);
    }
    g_part[((h * RC + rc) * TT) + col] = s;
}

// ---------------- 2) k / v / grouped-q norms: one warp per (h,t) ----------------
__global__ void norms_kvq_kernel(const float* __restrict__ k,
                                 const float* __restrict__ v,
                                 const float* __restrict__ q) {
    int warp = (blockIdx.x * blockDim.x + threadIdx.x) >> 5;
    int lane = threadIdx.x & 31;
    if (warp >= HH * TT) return;
    int h = warp / TT;
    int t = warp % TT;

    // key norm: 128 floats = 32 float4 lanes
    const float4* kp = (const float4*)(k + ((size_t)(h * TT + t)) * DD);
    float4 a = kp[lane];
    float ks = a.x * a.x + a.y * a.y + a.z * a.z + a.w * a.w;

    const float4* vp = (const float4*)(v + ((size_t)(h * TT + t)) * DD);
    float4 b = vp[lane];
    float vs = b.x * b.x + b.y * b.y + b.z * b.z + b.w * b.w;

    // q mean over group of 4 heads, then norm
    float4 acc = make_float4(0.f, 0.f, 0.f, 0.f);
#pragma unroll
    for (int g = 0; g < 4; ++g) {
        const float4* qp = (const float4*)(q + ((size_t)((h * 4 + g) * TT + t)) * DD);
        float4 u = qp[lane];
        acc.x += u.x; acc.y += u.y; acc.z += u.z; acc.w += u.w;
    }
    acc.x *= 0.25f; acc.y *= 0.25f; acc.z *= 0.25f; acc.w *= 0.25f;
    float qs = acc.x * acc.x + acc.y * acc.y + acc.z * acc.z + acc.w * acc.w;

#pragma unroll
    for (int o = 16; o > 0; o >>= 1) {
        ks += __shfl_xor_sync(0xffffffffu, ks, o);
        vs += __shfl_xor_sync(0xffffffffu, vs, o);
        qs += __shfl_xor_sync(0xffffffffu, qs, o);
    }
    if (lane == 0) {
        g_knorm[warp] = sqrtf(ks);
        g_vnorm[warp] = sqrtf(vs);
        g_qnorm[warp] = sqrtf(qs);
    }
}

// ---------------- 3) emb norm: one block per t over 4096 floats ----------------
__global__ void emb_norm_kernel(const float* __restrict__ x) {
    int t = blockIdx.x;
    const float4* xp = (const float4*)(x + (size_t)t * MM);
    float s = 0.0f;
    for (int i = threadIdx.x; i < MM / 4; i += blockDim.x) {
        float4 u = xp[i];
        s += u.x * u.x + u.y * u.y + u.z * u.z + u.w * u.w;
    }
#pragma unroll
    for (int o = 16; o > 0; o >>= 1) s += __shfl_xor_sync(0xffffffffu, s, o);
    __shared__ float red[8];
    int lane = threadIdx.x & 31, w = threadIdx.x >> 5;
    if (lane == 0) red[w] = s;
    __syncthreads();
    if (threadIdx.x == 0) {
        float tot = 0.0f;
#pragma unroll
        for (int i = 0; i < 8; ++i) tot += red[i];
        g_enorm[t] = sqrtf(tot);
    }
}

// ---------------- 4) finalize: reduce partials + MLP -> priority ----------------
__global__ void finalize_kernel(const float* __restrict__ W1,
                                const float* __restrict__ b1,
                                const float* __restrict__ W2,
                                const float* __restrict__ b2) {
    int idx = blockIdx.x * 256 + threadIdx.x;  // 0..16383, one h per block
    int h = idx >> 11;
    int t = idx & (TT - 1);

    __shared__ float sW1[50], sb1[10], sW2[10], sb2;
    if (threadIdx.x < 50) sW1[threadIdx.x] = W1[h * 50 + threadIdx.x];
    if (threadIdx.x < 10) {
        sb1[threadIdx.x] = b1[h * 10 + threadIdx.x];
        sW2[threadIdx.x] = W2[h * 10 + threadIdx.x];
    }
    if (threadIdx.x == 0) sb2 = b2[h];
    __syncthreads();

    float s = 0.0f;
#pragma unroll
    for (int rc = 0; rc < RC; ++rc) s += g_part[(h * RC + rc) * TT + t];

    float f[5];
    f[0] = s / (float)(TT - t);
    f[1] = g_knorm[idx];
    f[2] = g_vnorm[idx];
    f[3] = g_qnorm[idx];
    f[4] = g_enorm[t];

    float p = sb2;
#pragma unroll
    for (int kk = 0; kk < 10; ++kk) {
        float hsum = sb1[kk];
#pragma unroll
        for (int ff = 0; ff < 5; ++ff) hsum += f[ff] * sW1[ff * 10 + kk];
        p += fmaxf(hsum, 0.0f) * sW2[kk];
    }
    g_prio[idx] = p;
}

// ---------------- 5) per-h top-512 via full bitonic sort + index sort ----------------
__device__ __forceinline__ bool before_(float va, int ia, float vb, int ib) {
    // true if (va,ia) should come before (vb,ib): higher value, ties -> lower index
    return (va > vb) || (va == vb && ia < ib);
}

__global__ void topk_sort_kernel(float* __restrict__ out_idx_as_float) {
    __shared__ float sval[TT];
    __shared__ int   sidx[TT];
    __shared__ int   stop[LL];
    int h = blockIdx.x;
    int tid = threadIdx.x;

    for (int i = tid; i < TT; i += 1024) {
        sval[i] = g_prio[h * TT + i];
        sidx[i] = i;
    }
    __syncthreads();

    // bitonic sort: "before" order (descending value, tie lower idx first)
    for (int k = 2; k <= TT; k <<= 1) {
        for (int j = k >> 1; j > 0; j >>= 1) {
            for (int i = tid; i < TT; i += 1024) {
                int ixj = i ^ j;
                if (ixj > i) {
                    float va = sval[i], vb = sval[ixj];
                    int ia = sidx[i], ib = sidx[ixj];
                    bool up = ((i & k) == 0);
                    bool sw = up ? before_(vb, ib, va, ia)
                                 : before_(va, ia, vb, ib);
                    if (sw) {
                        sval[i] = vb; sval[ixj] = va;
                        sidx[i] = ib; sidx[ixj] = ia;
                    }
                }
            }
            __syncthreads();
        }
    }

    // take top-512 indices, sort ascending
    if (tid < LL) stop[tid] = sidx[tid];
    __syncthreads();
    for (int k = 2; k <= LL; k <<= 1) {
        for (int j = k >> 1; j > 0; j >>= 1) {
            if (tid < LL) {
                int ixj = tid ^ j;
                if (ixj > tid) {
                    int a = stop[tid], b = stop[ixj];
                    bool up = ((tid & k) == 0);
                    bool sw = up ? (b < a) : (a < b);
                    if (sw) { stop[tid] = b; stop[ixj] = a; }
                }
            }
            __syncthreads();
        }
    }
    if (tid < LL) {
        g_keep[h * LL + tid] = stop[tid];
        out_idx_as_float[h * LL + tid] = (float)stop[tid];
    }
}

// ---------------- 6) gather k/v rows ----------------
__global__ void gather_kernel(const float* __restrict__ k,
                              const float* __restrict__ v,
                              float* __restrict__ out) {
    int r = blockIdx.x;          // 0..4095 = h*512 + l
    int h = r >> 9;
    int t = g_keep[r];
    const float4* kp = (const float4*)(k + ((size_t)(h * TT + t)) * DD);
    const float4* vp = (const float4*)(v + ((size_t)(h * TT + t)) * DD);
    float4* ok = (float4*)(out + (size_t)HH * LL + (size_t)r * DD);
    float4* ov = (float4*)(out + (size_t)HH * LL + (size_t)HH * LL * DD + (size_t)r * DD);
    int i = threadIdx.x;         // 32 threads = 32 float4
    ok[i] = kp[i];
    ov[i] = vp[i];
}

// ---------------- launch ----------------
extern "C" void kernel_launch(void* const* d_in, const int* in_sizes, int n_in,
                              void* d_out, int out_size) {
    // metadata order: input_pos, k_val, v_val, query, x, attn, W1, b1, W2, b2
    const float* k    = (const float*)d_in[1];
    const float* v    = (const float*)d_in[2];
    const float* q    = (const float*)d_in[3];
    const float* x    = (const float*)d_in[4];
    const float* attn = (const float*)d_in[5];
    const float* W1   = (const float*)d_in[6];
    const float* b1   = (const float*)d_in[7];
    const float* W2   = (const float*)d_in[8];
    const float* b2   = (const float*)d_in[9];
    float* out = (float*)d_out;  // [keep_idxs(4096) | k_out(524288) | v_out(524288)]

    attn_partial_kernel<<<dim3(TT / 256, RC, HH), 256>>>(attn);
    norms_kvq_kernel<<<(HH * TT) / 8, 256>>>(k, v, q);
    emb_norm_kernel<<<TT, 256>>>(x);
    finalize_kernel<<<(HH * TT) / 256, 256>>>(W1, b1, W2, b2);
    topk_sort_kernel<<<HH, 1024>>>(out);
    gather_kernel<<<HH * LL, 32>>>(k, v, out);
}

// round 5
// speedup vs baseline: 1.5263x; 1.5263x over previous
#include <cuda_runtime.h>
#include <math.h>

#define TT 2048
#define HH 8
#define DD 128
#define MM 4096
#define LL 512
#define RC 32                     // row chunks for attn column-sum
#define ROWS_PER_CHUNK (TT / RC)  // 64

// ---------------- device scratch (no allocations allowed) ----------------
__device__ float g_part[HH * RC * TT];   // attn partial column sums (2 MB)
__device__ float g_knorm[HH * TT];
__device__ float g_vnorm[HH * TT];
__device__ float g_qnorm[HH * TT];
__device__ float g_enorm[TT];
__device__ int   g_keep[HH * LL];

// ---------------- 1) attn weighted column partial sums (float4) ----------------
// sum over 64 rows of attn[h, i, t] * (i+1), 4 columns per thread.
// grid: (TT/4/256=2, RC, HH) = 512 CTAs, block 256.
__global__ void attn_partial_kernel(const float* __restrict__ attn) {
    int c4  = blockIdx.x * 256 + threadIdx.x;   // float4 column index 0..511
    int rc  = blockIdx.y;
    int h   = blockIdx.z;
    int row0 = rc * ROWS_PER_CHUNK;
    const float4* base = (const float4*)attn + ((size_t)(h * TT + row0) * TT >> 2) + c4;
    float4 s = make_float4(0.f, 0.f, 0.f, 0.f);
#pragma unroll 8
    for (int i = 0; i < ROWS_PER_CHUNK; ++i) {
        float4 a = base[(size_t)i * (TT / 4)];
        float w = (float)(row0 + i + 1);
        s.x += a.x * w; s.y += a.y * w; s.z += a.z * w; s.w += a.w * w;
    }
    ((float4*)&g_part[(h * RC + rc) * TT])[c4] = s;
}

// ---------------- 2) fused norms: emb (blocks 0..TT-1) + k/v/q (rest) ----------------
__global__ void norms_kernel(const float* __restrict__ k,
                             const float* __restrict__ v,
                             const float* __restrict__ q,
                             const float* __restrict__ x) {
    if (blockIdx.x < TT) {
        // emb norm: one block per t over 4096 floats
        int t = blockIdx.x;
        const float4* xp = (const float4*)(x + (size_t)t * MM);
        float s = 0.0f;
        for (int i = threadIdx.x; i < MM / 4; i += 256) {
            float4 u = xp[i];
            s += u.x * u.x + u.y * u.y + u.z * u.z + u.w * u.w;
        }
#pragma unroll
        for (int o = 16; o > 0; o >>= 1) s += __shfl_xor_sync(0xffffffffu, s, o);
        __shared__ float red[8];
        int lane = threadIdx.x & 31, w = threadIdx.x >> 5;
        if (lane == 0) red[w] = s;
        __syncthreads();
        if (threadIdx.x == 0) {
            float tot = 0.0f;
#pragma unroll
            for (int i = 0; i < 8; ++i) tot += red[i];
            g_enorm[t] = sqrtf(tot);
        }
    } else {
        // kvq norms: one warp per (h,t)
        int warp = (blockIdx.x - TT) * 8 + (threadIdx.x >> 5);
        int lane = threadIdx.x & 31;
        int h = warp >> 11;
        int t = warp & (TT - 1);

        const float4* kp = (const float4*)(k + ((size_t)(h * TT + t)) * DD);
        float4 a = kp[lane];
        float ks = a.x * a.x + a.y * a.y + a.z * a.z + a.w * a.w;

        const float4* vp = (const float4*)(v + ((size_t)(h * TT + t)) * DD);
        float4 b = vp[lane];
        float vs = b.x * b.x + b.y * b.y + b.z * b.z + b.w * b.w;

        float4 acc = make_float4(0.f, 0.f, 0.f, 0.f);
#pragma unroll
        for (int g = 0; g < 4; ++g) {
            const float4* qp = (const float4*)(q + ((size_t)((h * 4 + g) * TT + t)) * DD);
            float4 u = qp[lane];
            acc.x += u.x; acc.y += u.y; acc.z += u.z; acc.w += u.w;
        }
        acc.x *= 0.25f; acc.y *= 0.25f; acc.z *= 0.25f; acc.w *= 0.25f;
        float qs = acc.x * acc.x + acc.y * acc.y + acc.z * acc.z + acc.w * acc.w;

#pragma unroll
        for (int o = 16; o > 0; o >>= 1) {
            ks += __shfl_xor_sync(0xffffffffu, ks, o);
            vs += __shfl_xor_sync(0xffffffffu, vs, o);
            qs += __shfl_xor_sync(0xffffffffu, qs, o);
        }
        if (lane == 0) {
            g_knorm[warp] = sqrtf(ks);
            g_vnorm[warp] = sqrtf(vs);
            g_qnorm[warp] = sqrtf(qs);
        }
    }
}

// ---------------- 3) fused priority + radix-select top-512 ----------------
// One block per head, 1024 threads. Selection = exact top-512 by value with
// ties -> lower index (matches lax.top_k), output indices sorted ascending
// (stable t-order compaction).
__global__ void __launch_bounds__(1024, 1)
prio_topk_kernel(const float* __restrict__ W1, const float* __restrict__ b1,
                 const float* __restrict__ W2, const float* __restrict__ b2,
                 float* __restrict__ out_idx_as_float) {
    int h = blockIdx.x;
    int tid = threadIdx.x;
    int lane = tid & 31, wid = tid >> 5;

    __shared__ unsigned su[TT];         // order-transformed priority bits
    __shared__ unsigned hist[256];
    __shared__ unsigned wsum[32];
    __shared__ unsigned s_prefix;
    __shared__ int      s_rem;
    __shared__ float sW1[50], sb1[10], sW2[10], sb2;

    if (tid < 50) sW1[tid] = W1[h * 50 + tid];
    if (tid >= 64 && tid < 74) {
        sb1[tid - 64] = b1[h * 10 + tid - 64];
        sW2[tid - 64] = W2[h * 10 + tid - 64];
    }
    if (tid == 96) sb2 = b2[h];
    if (tid == 0) { s_prefix = 0u; s_rem = LL; }
    __syncthreads();

    // ---- priorities for t = tid, tid+1024 ----
    for (int t = tid; t < TT; t += 1024) {
        float s = 0.0f;
#pragma unroll
        for (int rc = 0; rc < RC; ++rc) s += g_part[(h * RC + rc) * TT + t];
        float f0 = s / (float)(TT - t);
        float f1 = g_knorm[h * TT + t];
        float f2 = g_vnorm[h * TT + t];
        float f3 = g_qnorm[h * TT + t];
        float f4 = g_enorm[t];

        float p = sb2;
#pragma unroll
        for (int kk = 0; kk < 10; ++kk) {
            float hs = sb1[kk];
            hs += f0 * sW1[kk];
            hs += f1 * sW1[10 + kk];
            hs += f2 * sW1[20 + kk];
            hs += f3 * sW1[30 + kk];
            hs += f4 * sW1[40 + kk];
            p += fmaxf(hs, 0.0f) * sW2[kk];
        }
        unsigned u = __float_as_uint(p);
        u = (u & 0x80000000u) ? ~u : (u | 0x80000000u);  // monotone order map
        su[t] = u;
    }
    __syncthreads();

    // ---- 4-pass radix select of the 512th largest value (exact bits) ----
    for (int pass = 0; pass < 4; ++pass) {
        int shift = 24 - 8 * pass;
        if (tid < 256) hist[tid] = 0u;
        __syncthreads();
        unsigned pref = s_prefix;
#pragma unroll
        for (int t = tid; t < TT; t += 1024) {
            unsigned u = su[t];
            bool cand = (pass == 0) || ((u >> (shift + 8)) == (pref >> (shift + 8)));
            if (cand) atomicAdd(&hist[(u >> shift) & 255u], 1u);
        }
        __syncthreads();
        if (tid < 32) {
            int rem = s_rem;
            unsigned pfx = s_prefix;
            __syncwarp();
            unsigned local[8];
            unsigned lsum = 0;
#pragma unroll
            for (int i = 0; i < 8; ++i) { local[i] = hist[255 - (tid * 8 + i)]; lsum += local[i]; }
            unsigned inc = lsum;
#pragma unroll
            for (int o = 1; o < 32; o <<= 1) {
                unsigned n = __shfl_up_sync(0xffffffffu, inc, o);
                if (lane >= o) inc += n;
            }
            unsigned cum = inc - lsum;   // count in bins strictly above my group
#pragma unroll
            for (int i = 0; i < 8; ++i) {
                unsigned above = cum;
                cum += local[i];
                int bin = 255 - (tid * 8 + i);
                if (above < (unsigned)rem && cum >= (unsigned)rem) {
                    s_prefix = pfx | ((unsigned)bin << shift);
                    s_rem = rem - (int)above;
                }
            }
        }
        __syncthreads();
    }

    unsigned thr = s_prefix;     // exact value of the 512th largest
    unsigned extra = (unsigned)s_rem;  // # of (== thr) elements to keep (lowest t first)

    // ---- stable compaction: selected = (u > thr) || (u == thr && eq_rank < extra)
    // thread handles t0 = 2*tid, t1 = 2*tid+1 (preserves ascending t order)
    int t0 = 2 * tid, t1 = 2 * tid + 1;
    unsigned u0 = su[t0], u1 = su[t1];
    unsigned gt0 = (u0 > thr), eq0 = (u0 == thr);
    unsigned gt1 = (u1 > thr), eq1 = (u1 == thr);
    unsigned cnt = (gt0 + gt1) | ((eq0 + eq1) << 16);

    unsigned inc = cnt;
#pragma unroll
    for (int o = 1; o < 32; o <<= 1) {
        unsigned n = __shfl_up_sync(0xffffffffu, inc, o);
        if (lane >= o) inc += n;
    }
    if (lane == 31) wsum[wid] = inc;
    __syncthreads();
    if (tid < 32) {
        unsigned a = wsum[tid];
        unsigned in2 = a;
#pragma unroll
        for (int o = 1; o < 32; o <<= 1) {
            unsigned n = __shfl_up_sync(0xffffffffu, in2, o);
            if (lane >= o) in2 += n;
        }
        wsum[tid] = in2 - a;   // exclusive warp offsets
    }
    __syncthreads();
    unsigned excl = wsum[wid] + inc - cnt;     // packed exclusive prefix
    unsigned gt_b = excl & 0xffffu;
    unsigned eq_b = excl >> 16;

    if (gt0 || (eq0 && eq_b < extra)) {
        unsigned pos = gt_b + min(eq_b, extra);
        g_keep[h * LL + pos] = t0;
        out_idx_as_float[h * LL + pos] = (float)t0;
    }
    gt_b += gt0; eq_b += eq0;
    if (gt1 || (eq1 && eq_b < extra)) {
        unsigned pos = gt_b + min(eq_b, extra);
        g_keep[h * LL + pos] = t1;
        out_idx_as_float[h * LL + pos] = (float)t1;
    }
}

// ---------------- 4) gather k/v rows ----------------
__global__ void gather_kernel(const float* __restrict__ k,
                              const float* __restrict__ v,
                              float* __restrict__ out) {
    int r = blockIdx.x;          // 0..4095 = h*512 + l
    int h = r >> 9;
    int t = g_keep[r];
    const float4* kp = (const float4*)(k + ((size_t)(h * TT + t)) * DD);
    const float4* vp = (const float4*)(v + ((size_t)(h * TT + t)) * DD);
    float4* ok = (float4*)(out + (size_t)HH * LL + (size_t)r * DD);
    float4* ov = (float4*)(out + (size_t)HH * LL + (size_t)HH * LL * DD + (size_t)r * DD);
    int i = threadIdx.x;         // 32 threads = 32 float4
    ok[i] = kp[i];
    ov[i] = vp[i];
}

// ---------------- launch ----------------
extern "C" void kernel_launch(void* const* d_in, const int* in_sizes, int n_in,
                              void* d_out, int out_size) {
    // metadata order: input_pos, k_val, v_val, query, x, attn, W1, b1, W2, b2
    const float* k    = (const float*)d_in[1];
    const float* v    = (const float*)d_in[2];
    const float* q    = (const float*)d_in[3];
    const float* x    = (const float*)d_in[4];
    const float* attn = (const float*)d_in[5];
    const float* W1   = (const float*)d_in[6];
    const float* b1   = (const float*)d_in[7];
    const float* W2   = (const float*)d_in[8];
    const float* b2   = (const float*)d_in[9];
    float* out = (float*)d_out;  // [keep_idxs(4096) | k_out(524288) | v_out(524288)]

    attn_partial_kernel<<<dim3(TT / 4 / 256, RC, HH), 256>>>(attn);
    norms_kernel<<<TT + (HH * TT) / 8, 256>>>(k, v, q, x);
    prio_topk_kernel<<<HH, 1024>>>(W1, b1, W2, b2, out);
    gather_kernel<<<HH * LL, 32>>>(k, v, out);
}